// round 7
// baseline (speedup 1.0000x reference)
#include <cuda_runtime.h>

// GRU: B=4096, T=512, I=32, H=64. out = final hidden (B, H) fp32.
// 128 CTAs x 512 threads. Per SMSP group s (w&3), 4 warps:
//   role0/role1 (h-warps): recurrent GEMM k-split 32/32, epilogue rows 0-2 / 3-5
//   role2/role3 (x-warps): x-projection for step t+1 ROW-split 0-3 / 4-7,
//                          scheduled AFTER bar1 so it overlaps the epilogue.
// role3 also finishes rows 6-7 (keeps its XP rows 6-7 in registers).
// All exchange smsp-local via named barriers. Math: packed fma.rn.f32x2.

#define THREADS      512
#define ROWS_PER_CTA 32
#define I_DIM        32
#define H_DIM        64
#define G_DIM        192
#define S_DUP        68

#define WS_FLOATS    (96 * G_DIM)        // 18432
#define HD_FLOATS    (H_DIM * S_DUP)     // 4352
#define XD_FLOATS    (I_DIM * S_DUP)     // 2176 (single buffer)
#define SC_U64       (2 * 4 * 8 * 3 * 32)   // contrib, smsp, row, acc, lane
#define XP_U64       (2 * 4 * 6 * 3 * 32)   // parity, smsp, rows0-5, acc, lane
#define SMEM_BYTES   ((WS_FLOATS + HD_FLOATS + XD_FLOATS) * 4 + (SC_U64 + XP_U64) * 8)

typedef unsigned long long u64;

__device__ __forceinline__ void fma2(u64& d, u64 a, u64 b) {
    asm("fma.rn.f32x2 %0, %1, %2, %0;" : "+l"(d) : "l"(a), "l"(b));
}
__device__ __forceinline__ u64 add2(u64 a, u64 b) {
    u64 r;
    asm("add.rn.f32x2 %0, %1, %2;" : "=l"(r) : "l"(a), "l"(b));
    return r;
}
__device__ __forceinline__ float2 upk(u64 v) {
    float2 f;
    asm("mov.b64 {%0, %1}, %2;" : "=f"(f.x), "=f"(f.y) : "l"(v));
    return f;
}
__device__ __forceinline__ float tanh_hw(float x) {
    float y;
    asm("tanh.approx.f32 %0, %1;" : "=f"(y) : "f"(x));
    return y;
}
__device__ __forceinline__ float sig_hw(float x) {
    return fmaf(tanh_hw(0.5f * x), 0.5f, 0.5f);
}
__device__ __forceinline__ float tanh_acc(float x) {
    return __fdividef(2.0f, 1.0f + __expf(-2.0f * x)) - 1.0f;
}
__device__ __forceinline__ void barx(int id) {
    asm volatile("bar.sync %0, %1;" :: "r"(id), "r"(128) : "memory");
}

struct GateB { float bR0, bR1, bZ0, bZ1, bIN0, bIN1, bHN0, bHN1; };

__device__ __forceinline__ void gate_row(u64 sR, u64 sZ, u64 sN, u64 sX,
                                         const GateB& b, float2& h01) {
    float2 uR = upk(sR), uZ = upk(sZ), uH = upk(sN), uX = upk(sX);
    float r0g = sig_hw(uR.x + b.bR0);
    float z0g = sig_hw(uZ.x + b.bZ0);
    float n0  = tanh_acc(uX.x + b.bIN0 + r0g * (uH.x + b.bHN0));
    float r1g = sig_hw(uR.y + b.bR1);
    float z1g = sig_hw(uZ.y + b.bZ1);
    float n1  = tanh_acc(uX.y + b.bIN1 + r1g * (uH.y + b.bHN1));
    h01.x = n0 + z0g * (h01.x - n0);
    h01.y = n1 + z1g * (h01.y - n1);
}

// h-GEMM k-step: 8 rows, accumulate r,z,hn
#define KSTEP_H(kk)                                                          \
    {                                                                        \
        const float* hk = &HD[(kk) * S_DUP + 2 * r0];                        \
        ulonglong2 A0 = *reinterpret_cast<const ulonglong2*>(hk);            \
        ulonglong2 A1 = *reinterpret_cast<const ulonglong2*>(hk + 4);        \
        ulonglong2 A2 = *reinterpret_cast<const ulonglong2*>(hk + 8);        \
        ulonglong2 A3 = *reinterpret_cast<const ulonglong2*>(hk + 12);       \
        const float* wk = &Ws[(kk) * G_DIM + j0];                            \
        u64 wr = *reinterpret_cast<const u64*>(wk);                          \
        u64 wz = *reinterpret_cast<const u64*>(wk + 64);                     \
        u64 wn = *reinterpret_cast<const u64*>(wk + 128);                    \
        fma2(aR[0], A0.x, wr); fma2(aR[1], A0.y, wr);                        \
        fma2(aR[2], A1.x, wr); fma2(aR[3], A1.y, wr);                        \
        fma2(aR[4], A2.x, wr); fma2(aR[5], A2.y, wr);                        \
        fma2(aR[6], A3.x, wr); fma2(aR[7], A3.y, wr);                        \
        fma2(aZ[0], A0.x, wz); fma2(aZ[1], A0.y, wz);                        \
        fma2(aZ[2], A1.x, wz); fma2(aZ[3], A1.y, wz);                        \
        fma2(aZ[4], A2.x, wz); fma2(aZ[5], A2.y, wz);                        \
        fma2(aZ[6], A3.x, wz); fma2(aZ[7], A3.y, wz);                        \
        fma2(aN[0], A0.x, wn); fma2(aN[1], A0.y, wn);                        \
        fma2(aN[2], A1.x, wn); fma2(aN[3], A1.y, wn);                        \
        fma2(aN[4], A2.x, wn); fma2(aN[5], A2.y, wn);                        \
        fma2(aN[6], A3.x, wn); fma2(aN[7], A3.y, wn);                        \
    }

// x-projection k-step: 4 rows at float offset OFF (0 -> rows 0-3, 8 -> 4-7)
#define KSTEP_X4(kk, OFF)                                                    \
    {                                                                        \
        const float* xk = &XD[(kk) * S_DUP + 2 * r0 + (OFF)];                \
        ulonglong2 A0 = *reinterpret_cast<const ulonglong2*>(xk);            \
        ulonglong2 A1 = *reinterpret_cast<const ulonglong2*>(xk + 4);        \
        const float* wk = &Ws[(H_DIM + (kk)) * G_DIM + j0];                  \
        u64 wr = *reinterpret_cast<const u64*>(wk);                          \
        u64 wz = *reinterpret_cast<const u64*>(wk + 64);                     \
        u64 wn = *reinterpret_cast<const u64*>(wk + 128);                    \
        fma2(aR[0], A0.x, wr); fma2(aR[1], A0.y, wr);                        \
        fma2(aR[2], A1.x, wr); fma2(aR[3], A1.y, wr);                        \
        fma2(aZ[0], A0.x, wz); fma2(aZ[1], A0.y, wz);                        \
        fma2(aZ[2], A1.x, wz); fma2(aZ[3], A1.y, wz);                        \
        fma2(aX[0], A0.x, wn); fma2(aX[1], A0.y, wn);                        \
        fma2(aX[2], A1.x, wn); fma2(aX[3], A1.y, wn);                        \
    }

#define SCI(g, l, a)  (((((g) * 4 + smsp) * 8 + (l)) * 3 + (a)) * 32 + c)
#define XPI(p, l, a)  (((((p) * 4 + smsp) * 6 + (l)) * 3 + (a)) * 32 + c)

#define HDWR(gr, hv)                                                                \
    *reinterpret_cast<float2*>(&HD[j0 * S_DUP + 2 * (gr)])       = make_float2((hv).x, (hv).x); \
    *reinterpret_cast<float2*>(&HD[(j0 + 1) * S_DUP + 2 * (gr)]) = make_float2((hv).y, (hv).y);

__global__ void __launch_bounds__(THREADS, 1)
gru_fwd_kernel(const float* __restrict__ seq,
               const float* __restrict__ W_ih,
               const float* __restrict__ W_hh,
               const float* __restrict__ b_ih,
               const float* __restrict__ b_hh,
               float* __restrict__ out,
               int B, int T)
{
    extern __shared__ float sm[];
    float* Ws  = sm;
    float* HD  = sm + WS_FLOATS;
    float* XD  = HD + HD_FLOATS;
    u64*   SCb = (u64*)(XD + XD_FLOATS);
    u64*   XPb = SCb + SC_U64;

    const int tid   = threadIdx.x;
    const int w     = tid >> 5;
    const int c     = tid & 31;
    const int smsp  = w & 3;
    const int role  = w >> 2;             // 0,1: h-warps  2,3: x-warps
    const int bb    = blockIdx.x * ROWS_PER_CTA;
    const int r0    = smsp * 8;
    const int j0    = 2 * c;
    const int barid = 1 + smsp;

    // ---- one-time init ----
    for (int idx = tid; idx < G_DIM * H_DIM; idx += THREADS) {
        int gg = idx / H_DIM, k = idx % H_DIM;
        Ws[k * G_DIM + gg] = W_hh[idx];
    }
    for (int idx = tid; idx < G_DIM * I_DIM; idx += THREADS) {
        int gg = idx / I_DIM, i = idx % I_DIM;
        Ws[(H_DIM + i) * G_DIM + gg] = W_ih[idx];
    }
    for (int idx = tid; idx < HD_FLOATS; idx += THREADS) HD[idx] = 0.0f;

    GateB gb;
    gb.bR0  = b_ih[j0]      + b_hh[j0];
    gb.bR1  = b_ih[j0 + 1]  + b_hh[j0 + 1];
    gb.bZ0  = b_ih[64 + j0] + b_hh[64 + j0];
    gb.bZ1  = b_ih[65 + j0] + b_hh[65 + j0];
    gb.bIN0 = b_ih[128 + j0]; gb.bIN1 = b_ih[129 + j0];
    gb.bHN0 = b_hh[128 + j0]; gb.bHN1 = b_hh[129 + j0];

    // stager role (h-warps): 64 slots/smsp = 8 rows x 8 float4 chunks
    const int q     = role * 32 + c;               // valid for role<2: [0,64)
    const int srow  = r0 + (q >> 3);
    const int scol4 = (q & 7) * 4;
    const float* xptr = seq + (size_t)(bb + srow) * T * I_DIM + scol4;

    float2 h0r = make_float2(0.f, 0.f), h1r = h0r, h2r = h0r;
    u64 pR6 = 0, pZ6 = 0, pX6 = 0, pR7 = 0, pZ7 = 0, pX7 = 0;

    float4 xn4 = make_float4(0.f, 0.f, 0.f, 0.f);

    // ---- prologue: stage x(0); preload x(1) ----
    if (role < 2) {
        float4 v0 = *reinterpret_cast<const float4*>(xptr);
        #pragma unroll
        for (int i = 0; i < 4; ++i) {
            float vv = (&v0.x)[i];
            *reinterpret_cast<float2*>(&XD[(scol4 + i) * S_DUP + 2 * srow]) =
                make_float2(vv, vv);
        }
        if (T > 1)
            xn4 = *reinterpret_cast<const float4*>(xptr + I_DIM);
    }
    __syncthreads();

    // prologue: XP(0) at parity 0
    if (role == 2) {
        u64 aR[4] = {0, 0, 0, 0}, aZ[4] = {0, 0, 0, 0}, aX[4] = {0, 0, 0, 0};
        #pragma unroll 8
        for (int k = 0; k < I_DIM; ++k) KSTEP_X4(k, 0)
        #pragma unroll
        for (int l = 0; l < 4; ++l) {
            XPb[XPI(0, l, 0)] = aR[l];
            XPb[XPI(0, l, 1)] = aZ[l];
            XPb[XPI(0, l, 2)] = aX[l];
        }
    } else if (role == 3) {
        u64 aR[4] = {0, 0, 0, 0}, aZ[4] = {0, 0, 0, 0}, aX[4] = {0, 0, 0, 0};
        #pragma unroll 8
        for (int k = 0; k < I_DIM; ++k) KSTEP_X4(k, 8)
        XPb[XPI(0, 4, 0)] = aR[0]; XPb[XPI(0, 4, 1)] = aZ[0]; XPb[XPI(0, 4, 2)] = aX[0];
        XPb[XPI(0, 5, 0)] = aR[1]; XPb[XPI(0, 5, 1)] = aZ[1]; XPb[XPI(0, 5, 2)] = aX[1];
        pR6 = aR[2]; pZ6 = aZ[2]; pX6 = aX[2];
        pR7 = aR[3]; pZ7 = aZ[3]; pX7 = aX[3];
    }
    __syncthreads();

    for (int t = 0; t < T; ++t) {
        const int par  = t & 1;            // parity of XP(t)
        const int par2 = par ^ 1;          // parity of XP(t+1)

        if (role < 2) {
            // ---- phase 1: stage x(t+1), prefetch x(t+2), h-GEMM ----
            if (t + 1 < T) {
                #pragma unroll
                for (int i = 0; i < 4; ++i) {
                    float vv = (&xn4.x)[i];
                    *reinterpret_cast<float2*>(&XD[(scol4 + i) * S_DUP + 2 * srow]) =
                        make_float2(vv, vv);
                }
            }
            if (t + 2 < T)
                xn4 = *reinterpret_cast<const float4*>(xptr + (size_t)(t + 2) * I_DIM);

            u64 aR[8], aZ[8], aN[8];
            #pragma unroll
            for (int i = 0; i < 8; ++i) { aR[i] = 0; aZ[i] = 0; aN[i] = 0; }
            const int koff = role * 32;
            #pragma unroll 8
            for (int k = 0; k < 32; ++k) KSTEP_H(koff + k)

            if (role == 0) {
                #pragma unroll
                for (int l = 3; l < 8; ++l) {
                    SCb[SCI(0, l, 0)] = aR[l];
                    SCb[SCI(0, l, 1)] = aZ[l];
                    SCb[SCI(0, l, 2)] = aN[l];
                }
            } else {
                SCb[SCI(1, 0, 0)] = aR[0]; SCb[SCI(1, 0, 1)] = aZ[0]; SCb[SCI(1, 0, 2)] = aN[0];
                SCb[SCI(1, 1, 0)] = aR[1]; SCb[SCI(1, 1, 1)] = aZ[1]; SCb[SCI(1, 1, 2)] = aN[1];
                SCb[SCI(1, 2, 0)] = aR[2]; SCb[SCI(1, 2, 1)] = aZ[2]; SCb[SCI(1, 2, 2)] = aN[2];
                SCb[SCI(1, 6, 0)] = aR[6]; SCb[SCI(1, 6, 1)] = aZ[6]; SCb[SCI(1, 6, 2)] = aN[6];
                SCb[SCI(1, 7, 0)] = aR[7]; SCb[SCI(1, 7, 1)] = aZ[7]; SCb[SCI(1, 7, 2)] = aN[7];
            }
            barx(barid);

            // ---- phase 2: epilogue (overlapped with x-warps' XP GEMM) ----
            if (role == 0) {
                gate_row(add2(add2(aR[0], SCb[SCI(1, 0, 0)]), XPb[XPI(par, 0, 0)]),
                         add2(add2(aZ[0], SCb[SCI(1, 0, 1)]), XPb[XPI(par, 0, 1)]),
                         add2(aN[0], SCb[SCI(1, 0, 2)]),
                         XPb[XPI(par, 0, 2)], gb, h0r);
                gate_row(add2(add2(aR[1], SCb[SCI(1, 1, 0)]), XPb[XPI(par, 1, 0)]),
                         add2(add2(aZ[1], SCb[SCI(1, 1, 1)]), XPb[XPI(par, 1, 1)]),
                         add2(aN[1], SCb[SCI(1, 1, 2)]),
                         XPb[XPI(par, 1, 2)], gb, h1r);
                gate_row(add2(add2(aR[2], SCb[SCI(1, 2, 0)]), XPb[XPI(par, 2, 0)]),
                         add2(add2(aZ[2], SCb[SCI(1, 2, 1)]), XPb[XPI(par, 2, 1)]),
                         add2(aN[2], SCb[SCI(1, 2, 2)]),
                         XPb[XPI(par, 2, 2)], gb, h2r);
                HDWR(r0 + 0, h0r)
                HDWR(r0 + 1, h1r)
                HDWR(r0 + 2, h2r)
            } else {
                gate_row(add2(add2(aR[3], SCb[SCI(0, 3, 0)]), XPb[XPI(par, 3, 0)]),
                         add2(add2(aZ[3], SCb[SCI(0, 3, 1)]), XPb[XPI(par, 3, 1)]),
                         add2(aN[3], SCb[SCI(0, 3, 2)]),
                         XPb[XPI(par, 3, 2)], gb, h0r);
                gate_row(add2(add2(aR[4], SCb[SCI(0, 4, 0)]), XPb[XPI(par, 4, 0)]),
                         add2(add2(aZ[4], SCb[SCI(0, 4, 1)]), XPb[XPI(par, 4, 1)]),
                         add2(aN[4], SCb[SCI(0, 4, 2)]),
                         XPb[XPI(par, 4, 2)], gb, h1r);
                gate_row(add2(add2(aR[5], SCb[SCI(0, 5, 0)]), XPb[XPI(par, 5, 0)]),
                         add2(add2(aZ[5], SCb[SCI(0, 5, 1)]), XPb[XPI(par, 5, 1)]),
                         add2(aN[5], SCb[SCI(0, 5, 2)]),
                         XPb[XPI(par, 5, 2)], gb, h2r);
                HDWR(r0 + 3, h0r)
                HDWR(r0 + 4, h1r)
                HDWR(r0 + 5, h2r)
            }
            barx(barid);
        } else if (role == 2) {
            barx(barid);
            // ---- phase 2: XP(t+1) rows 0-3 ----
            if (t + 1 < T) {
                u64 aR[4] = {0, 0, 0, 0}, aZ[4] = {0, 0, 0, 0}, aX[4] = {0, 0, 0, 0};
                #pragma unroll 8
                for (int k = 0; k < I_DIM; ++k) KSTEP_X4(k, 0)
                #pragma unroll
                for (int l = 0; l < 4; ++l) {
                    XPb[XPI(par2, l, 0)] = aR[l];
                    XPb[XPI(par2, l, 1)] = aZ[l];
                    XPb[XPI(par2, l, 2)] = aX[l];
                }
            }
            barx(barid);
        } else {
            barx(barid);
            // ---- phase 2: epilogue rows 6-7, then XP(t+1) rows 4-7 ----
            gate_row(add2(add2(SCb[SCI(0, 6, 0)], SCb[SCI(1, 6, 0)]), pR6),
                     add2(add2(SCb[SCI(0, 6, 1)], SCb[SCI(1, 6, 1)]), pZ6),
                     add2(SCb[SCI(0, 6, 2)], SCb[SCI(1, 6, 2)]),
                     pX6, gb, h0r);
            gate_row(add2(add2(SCb[SCI(0, 7, 0)], SCb[SCI(1, 7, 0)]), pR7),
                     add2(add2(SCb[SCI(0, 7, 1)], SCb[SCI(1, 7, 1)]), pZ7),
                     add2(SCb[SCI(0, 7, 2)], SCb[SCI(1, 7, 2)]),
                     pX7, gb, h1r);
            HDWR(r0 + 6, h0r)
            HDWR(r0 + 7, h1r)

            if (t + 1 < T) {
                u64 aR[4] = {0, 0, 0, 0}, aZ[4] = {0, 0, 0, 0}, aX[4] = {0, 0, 0, 0};
                #pragma unroll 8
                for (int k = 0; k < I_DIM; ++k) KSTEP_X4(k, 8)
                XPb[XPI(par2, 4, 0)] = aR[0]; XPb[XPI(par2, 4, 1)] = aZ[0]; XPb[XPI(par2, 4, 2)] = aX[0];
                XPb[XPI(par2, 5, 0)] = aR[1]; XPb[XPI(par2, 5, 1)] = aZ[1]; XPb[XPI(par2, 5, 2)] = aX[1];
                pR6 = aR[2]; pZ6 = aZ[2]; pX6 = aX[2];
                pR7 = aR[3]; pZ7 = aZ[3]; pX7 = aX[3];
            }
            barx(barid);
        }
    }

    // ---- final output ----
    if (role == 0) {
        *reinterpret_cast<float2*>(&out[(size_t)(bb + r0 + 0) * H_DIM + j0]) = h0r;
        *reinterpret_cast<float2*>(&out[(size_t)(bb + r0 + 1) * H_DIM + j0]) = h1r;
        *reinterpret_cast<float2*>(&out[(size_t)(bb + r0 + 2) * H_DIM + j0]) = h2r;
    } else if (role == 1) {
        *reinterpret_cast<float2*>(&out[(size_t)(bb + r0 + 3) * H_DIM + j0]) = h0r;
        *reinterpret_cast<float2*>(&out[(size_t)(bb + r0 + 4) * H_DIM + j0]) = h1r;
        *reinterpret_cast<float2*>(&out[(size_t)(bb + r0 + 5) * H_DIM + j0]) = h2r;
    } else if (role == 3) {
        *reinterpret_cast<float2*>(&out[(size_t)(bb + r0 + 6) * H_DIM + j0]) = h0r;
        *reinterpret_cast<float2*>(&out[(size_t)(bb + r0 + 7) * H_DIM + j0]) = h1r;
    }
}

extern "C" void kernel_launch(void* const* d_in, const int* in_sizes, int n_in,
                              void* d_out, int out_size) {
    const float* seq  = (const float*)d_in[0];
    const float* W_ih = (const float*)d_in[1];
    const float* W_hh = (const float*)d_in[2];
    const float* b_ih = (const float*)d_in[3];
    const float* b_hh = (const float*)d_in[4];
    float* out = (float*)d_out;

    const int B = out_size / H_DIM;
    const int T = in_sizes[0] / (B * I_DIM);

    cudaFuncSetAttribute(gru_fwd_kernel,
                         cudaFuncAttributeMaxDynamicSharedMemorySize, SMEM_BYTES);

    const int grid = (B + ROWS_PER_CTA - 1) / ROWS_PER_CTA;
    gru_fwd_kernel<<<grid, THREADS, SMEM_BYTES>>>(seq, W_ih, W_hh, b_ih, b_hh,
                                                  out, B, T);
}

// round 8
// speedup vs baseline: 1.8755x; 1.8755x over previous
#include <cuda_runtime.h>

// GRU: B=4096, T=512, I=32, H=64. out = final hidden (B, H) fp32.
// 128 CTAs x 384 threads (>=160 regs/thread available; 512 thr caps at 128 and
// regresses). Per SMSP group s (w&3): 2 h-warps + 1 x-warp.
//   Phase 1: h-warps run the recurrent GEMM k-split 32/32 and ship partials.
//            x-warp waits at bar1.
//   Phase 2: h-warps do the gate epilogue (rows 0-3 / 4-7) and stage x(t+2);
//            x-warp computes XP(t+1) (the x-projection) -> hides the epilogue.
// XD and XP are parity double-buffered; SC write/read straddles bar1.
// Math: packed fma.rn.f32x2 on duplicated smem operands.

#define THREADS      384
#define ROWS_PER_CTA 32
#define I_DIM        32
#define H_DIM        64
#define G_DIM        192
#define S_DUP        68

#define WS_FLOATS    (96 * G_DIM)        // 18432
#define HD_FLOATS    (H_DIM * S_DUP)     // 4352
#define XD_FLOATS    (I_DIM * S_DUP)     // 2176 (x2 buffers)
#define SC_U64       (2 * 4 * 8 * 3 * 32)   // contrib, smsp, row, acc, lane
#define XP_U64       (2 * 4 * 8 * 3 * 32)   // parity, smsp, row, acc, lane
#define SMEM_BYTES   ((WS_FLOATS + HD_FLOATS + 2 * XD_FLOATS) * 4 + (SC_U64 + XP_U64) * 8)

typedef unsigned long long u64;

__device__ __forceinline__ void fma2(u64& d, u64 a, u64 b) {
    asm("fma.rn.f32x2 %0, %1, %2, %0;" : "+l"(d) : "l"(a), "l"(b));
}
__device__ __forceinline__ u64 add2(u64 a, u64 b) {
    u64 r;
    asm("add.rn.f32x2 %0, %1, %2;" : "=l"(r) : "l"(a), "l"(b));
    return r;
}
__device__ __forceinline__ float2 upk(u64 v) {
    float2 f;
    asm("mov.b64 {%0, %1}, %2;" : "=f"(f.x), "=f"(f.y) : "l"(v));
    return f;
}
__device__ __forceinline__ float tanh_hw(float x) {
    float y;
    asm("tanh.approx.f32 %0, %1;" : "=f"(y) : "f"(x));
    return y;
}
__device__ __forceinline__ float sig_hw(float x) {
    return fmaf(tanh_hw(0.5f * x), 0.5f, 0.5f);
}
__device__ __forceinline__ float tanh_acc(float x) {
    return __fdividef(2.0f, 1.0f + __expf(-2.0f * x)) - 1.0f;
}
__device__ __forceinline__ void barx(int id) {
    asm volatile("bar.sync %0, %1;" :: "r"(id), "r"(96) : "memory");
}

struct GateB { float bR0, bR1, bZ0, bZ1, bIN0, bIN1, bHN0, bHN1; };

__device__ __forceinline__ void gate_row(u64 sR, u64 sZ, u64 sN, u64 sX,
                                         const GateB& b, float2& h01) {
    float2 uR = upk(sR), uZ = upk(sZ), uH = upk(sN), uX = upk(sX);
    float r0g = sig_hw(uR.x + b.bR0);
    float z0g = sig_hw(uZ.x + b.bZ0);
    float n0  = tanh_acc(uX.x + b.bIN0 + r0g * (uH.x + b.bHN0));
    float r1g = sig_hw(uR.y + b.bR1);
    float z1g = sig_hw(uZ.y + b.bZ1);
    float n1  = tanh_acc(uX.y + b.bIN1 + r1g * (uH.y + b.bHN1));
    h01.x = n0 + z0g * (h01.x - n0);
    h01.y = n1 + z1g * (h01.y - n1);
}

// recurrent k-step: 8 rows, acc (aR, aZ, aN), A from HD
#define KSTEP_H(kk)                                                          \
    {                                                                        \
        const float* hk = &HD[(kk) * S_DUP + 2 * r0];                        \
        ulonglong2 A0 = *reinterpret_cast<const ulonglong2*>(hk);            \
        ulonglong2 A1 = *reinterpret_cast<const ulonglong2*>(hk + 4);        \
        ulonglong2 A2 = *reinterpret_cast<const ulonglong2*>(hk + 8);        \
        ulonglong2 A3 = *reinterpret_cast<const ulonglong2*>(hk + 12);       \
        const float* wk = &Ws[(kk) * G_DIM + j0];                            \
        u64 wr = *reinterpret_cast<const u64*>(wk);                          \
        u64 wz = *reinterpret_cast<const u64*>(wk + 64);                     \
        u64 wn = *reinterpret_cast<const u64*>(wk + 128);                    \
        fma2(aR[0], A0.x, wr); fma2(aR[1], A0.y, wr);                        \
        fma2(aR[2], A1.x, wr); fma2(aR[3], A1.y, wr);                        \
        fma2(aR[4], A2.x, wr); fma2(aR[5], A2.y, wr);                        \
        fma2(aR[6], A3.x, wr); fma2(aR[7], A3.y, wr);                        \
        fma2(aZ[0], A0.x, wz); fma2(aZ[1], A0.y, wz);                        \
        fma2(aZ[2], A1.x, wz); fma2(aZ[3], A1.y, wz);                        \
        fma2(aZ[4], A2.x, wz); fma2(aZ[5], A2.y, wz);                        \
        fma2(aZ[6], A3.x, wz); fma2(aZ[7], A3.y, wz);                        \
        fma2(aN[0], A0.x, wn); fma2(aN[1], A0.y, wn);                        \
        fma2(aN[2], A1.x, wn); fma2(aN[3], A1.y, wn);                        \
        fma2(aN[4], A2.x, wn); fma2(aN[5], A2.y, wn);                        \
        fma2(aN[6], A3.x, wn); fma2(aN[7], A3.y, wn);                        \
    }

// x-projection k-step: 8 rows, acc (aR, aZ, aX), A from XDp
#define KSTEP_X(kk, P)                                                       \
    {                                                                        \
        const float* xk = &(P)[(kk) * S_DUP + 2 * r0];                       \
        ulonglong2 A0 = *reinterpret_cast<const ulonglong2*>(xk);            \
        ulonglong2 A1 = *reinterpret_cast<const ulonglong2*>(xk + 4);        \
        ulonglong2 A2 = *reinterpret_cast<const ulonglong2*>(xk + 8);        \
        ulonglong2 A3 = *reinterpret_cast<const ulonglong2*>(xk + 12);       \
        const float* wk = &Ws[(H_DIM + (kk)) * G_DIM + j0];                  \
        u64 wr = *reinterpret_cast<const u64*>(wk);                          \
        u64 wz = *reinterpret_cast<const u64*>(wk + 64);                     \
        u64 wn = *reinterpret_cast<const u64*>(wk + 128);                    \
        fma2(aR[0], A0.x, wr); fma2(aR[1], A0.y, wr);                        \
        fma2(aR[2], A1.x, wr); fma2(aR[3], A1.y, wr);                        \
        fma2(aR[4], A2.x, wr); fma2(aR[5], A2.y, wr);                        \
        fma2(aR[6], A3.x, wr); fma2(aR[7], A3.y, wr);                        \
        fma2(aZ[0], A0.x, wz); fma2(aZ[1], A0.y, wz);                        \
        fma2(aZ[2], A1.x, wz); fma2(aZ[3], A1.y, wz);                        \
        fma2(aZ[4], A2.x, wz); fma2(aZ[5], A2.y, wz);                        \
        fma2(aZ[6], A3.x, wz); fma2(aZ[7], A3.y, wz);                        \
        fma2(aX[0], A0.x, wn); fma2(aX[1], A0.y, wn);                        \
        fma2(aX[2], A1.x, wn); fma2(aX[3], A1.y, wn);                        \
        fma2(aX[4], A2.x, wn); fma2(aX[5], A2.y, wn);                        \
        fma2(aX[6], A3.x, wn); fma2(aX[7], A3.y, wn);                        \
    }

#define SCI(g, l, a)  (((((g) * 4 + smsp) * 8 + (l)) * 3 + (a)) * 32 + c)
#define XPI(p, l, a)  (((((p) * 4 + smsp) * 8 + (l)) * 3 + (a)) * 32 + c)

#define HDWR(gr, hv)                                                                \
    *reinterpret_cast<float2*>(&HD[j0 * S_DUP + 2 * (gr)])       = make_float2((hv).x, (hv).x); \
    *reinterpret_cast<float2*>(&HD[(j0 + 1) * S_DUP + 2 * (gr)]) = make_float2((hv).y, (hv).y);

// epilogue for one row l owned by h-warp with partner contribution SC(og,...)
#define EPI_ROW(l, og, hv)                                                    \
    gate_row(add2(add2(aR[l], SCb[SCI(og, l, 0)]), XPb[XPI(par, l, 0)]),      \
             add2(add2(aZ[l], SCb[SCI(og, l, 1)]), XPb[XPI(par, l, 1)]),      \
             add2(aN[l], SCb[SCI(og, l, 2)]),                                 \
             XPb[XPI(par, l, 2)], gb, hv);

__global__ void __launch_bounds__(THREADS, 1)
gru_fwd_kernel(const float* __restrict__ seq,
               const float* __restrict__ W_ih,
               const float* __restrict__ W_hh,
               const float* __restrict__ b_ih,
               const float* __restrict__ b_hh,
               float* __restrict__ out,
               int B, int T)
{
    extern __shared__ float sm[];
    float* Ws  = sm;
    float* HD  = sm + WS_FLOATS;
    float* XD  = HD + HD_FLOATS;                  // 2 parity buffers
    u64*   SCb = (u64*)(XD + 2 * XD_FLOATS);
    u64*   XPb = SCb + SC_U64;

    const int tid   = threadIdx.x;
    const int w     = tid >> 5;
    const int c     = tid & 31;
    const int smsp  = (w < 8) ? (w & 3) : (w - 8);
    const int role  = w >> 2;                      // 0,1: h-warps, 2: x-warp
    const int bb    = blockIdx.x * ROWS_PER_CTA;
    const int r0    = smsp * 8;
    const int j0    = 2 * c;
    const int barid = 1 + smsp;

    // ---- one-time init ----
    for (int idx = tid; idx < G_DIM * H_DIM; idx += THREADS) {
        int gg = idx / H_DIM, k = idx % H_DIM;
        Ws[k * G_DIM + gg] = W_hh[idx];
    }
    for (int idx = tid; idx < G_DIM * I_DIM; idx += THREADS) {
        int gg = idx / I_DIM, i = idx % I_DIM;
        Ws[(H_DIM + i) * G_DIM + gg] = W_ih[idx];
    }
    for (int idx = tid; idx < HD_FLOATS; idx += THREADS) HD[idx] = 0.0f;

    GateB gb;
    gb.bR0  = b_ih[j0]      + b_hh[j0];
    gb.bR1  = b_ih[j0 + 1]  + b_hh[j0 + 1];
    gb.bZ0  = b_ih[64 + j0] + b_hh[64 + j0];
    gb.bZ1  = b_ih[65 + j0] + b_hh[65 + j0];
    gb.bIN0 = b_ih[128 + j0]; gb.bIN1 = b_ih[129 + j0];
    gb.bHN0 = b_hh[128 + j0]; gb.bHN1 = b_hh[129 + j0];

    // stager role (h-warps only): 64 slots/smsp = 8 rows x 8 float4 chunks
    const int q     = (role == 1 ? 32 : 0) + c;
    const int srow  = r0 + (q >> 3);
    const int scol4 = (q & 7) * 4;
    const float* xptr = seq + (size_t)(bb + srow) * T * I_DIM + scol4;

    float2 h0r = make_float2(0.f, 0.f), h1r = h0r, h2r = h0r, h3r = h0r;
    float4 xn4 = make_float4(0.f, 0.f, 0.f, 0.f);

    // ---- prologue: stage x(0)->XD[0], x(1)->XD[1] ----
    if (role < 2) {
        float4 v0 = *reinterpret_cast<const float4*>(xptr);
        #pragma unroll
        for (int i = 0; i < 4; ++i) {
            float vv = (&v0.x)[i];
            *reinterpret_cast<float2*>(&XD[(scol4 + i) * S_DUP + 2 * srow]) =
                make_float2(vv, vv);
        }
        if (T > 1) {
            float4 v1 = *reinterpret_cast<const float4*>(xptr + I_DIM);
            #pragma unroll
            for (int i = 0; i < 4; ++i) {
                float vv = (&v1.x)[i];
                *reinterpret_cast<float2*>(&XD[XD_FLOATS + (scol4 + i) * S_DUP + 2 * srow]) =
                    make_float2(vv, vv);
            }
        }
    }
    __syncthreads();

    // prologue: x-warp computes XP(0) into parity 0
    if (role == 2) {
        u64 aR[8], aZ[8], aX[8];
        #pragma unroll
        for (int i = 0; i < 8; ++i) { aR[i] = 0; aZ[i] = 0; aX[i] = 0; }
        const float* XDp = XD;
        #pragma unroll 8
        for (int k = 0; k < I_DIM; ++k) KSTEP_X(k, XDp)
        #pragma unroll
        for (int l = 0; l < 8; ++l) {
            XPb[XPI(0, l, 0)] = aR[l];
            XPb[XPI(0, l, 1)] = aZ[l];
            XPb[XPI(0, l, 2)] = aX[l];
        }
    }
    __syncthreads();

    for (int t = 0; t < T; ++t) {
        const int par  = t & 1;            // XP(t) parity; also staging target
        const int par2 = par ^ 1;          // XP(t+1) parity; x-warp reads XD[par2]

        if (role < 2) {
            // ---- phase 1: prefetch x(t+2), h-GEMM, ship SC ----
            if (t + 2 < T)
                xn4 = *reinterpret_cast<const float4*>(xptr + (size_t)(t + 2) * I_DIM);

            u64 aR[8], aZ[8], aN[8];
            #pragma unroll
            for (int i = 0; i < 8; ++i) { aR[i] = 0; aZ[i] = 0; aN[i] = 0; }
            const int koff = role * 32;
            #pragma unroll 8
            for (int k = 0; k < 32; ++k) KSTEP_H(koff + k)

            if (role == 0) {
                #pragma unroll
                for (int l = 4; l < 8; ++l) {
                    SCb[SCI(0, l, 0)] = aR[l];
                    SCb[SCI(0, l, 1)] = aZ[l];
                    SCb[SCI(0, l, 2)] = aN[l];
                }
            } else {
                #pragma unroll
                for (int l = 0; l < 4; ++l) {
                    SCb[SCI(1, l, 0)] = aR[l];
                    SCb[SCI(1, l, 1)] = aZ[l];
                    SCb[SCI(1, l, 2)] = aN[l];
                }
            }
            barx(barid);

            // ---- phase 2: stage x(t+2) into XD[par]; epilogue 4 rows ----
            if (t + 2 < T) {
                #pragma unroll
                for (int i = 0; i < 4; ++i) {
                    float vv = (&xn4.x)[i];
                    *reinterpret_cast<float2*>(&XD[par * XD_FLOATS + (scol4 + i) * S_DUP + 2 * srow]) =
                        make_float2(vv, vv);
                }
            }

            if (role == 0) {
                EPI_ROW(0, 1, h0r)
                EPI_ROW(1, 1, h1r)
                EPI_ROW(2, 1, h2r)
                EPI_ROW(3, 1, h3r)
                HDWR(r0 + 0, h0r)
                HDWR(r0 + 1, h1r)
                HDWR(r0 + 2, h2r)
                HDWR(r0 + 3, h3r)
            } else {
                EPI_ROW(4, 0, h0r)
                EPI_ROW(5, 0, h1r)
                EPI_ROW(6, 0, h2r)
                EPI_ROW(7, 0, h3r)
                HDWR(r0 + 4, h0r)
                HDWR(r0 + 5, h1r)
                HDWR(r0 + 6, h2r)
                HDWR(r0 + 7, h3r)
            }
            barx(barid);
        } else {
            // x-warp: wait out phase 1, then XP(t+1) during the epilogue window
            barx(barid);
            if (t + 1 < T) {
                u64 aR[8], aZ[8], aX[8];
                #pragma unroll
                for (int i = 0; i < 8; ++i) { aR[i] = 0; aZ[i] = 0; aX[i] = 0; }
                const float* XDp = XD + par2 * XD_FLOATS;
                #pragma unroll 8
                for (int k = 0; k < I_DIM; ++k) KSTEP_X(k, XDp)
                #pragma unroll
                for (int l = 0; l < 8; ++l) {
                    XPb[XPI(par2, l, 0)] = aR[l];
                    XPb[XPI(par2, l, 1)] = aZ[l];
                    XPb[XPI(par2, l, 2)] = aX[l];
                }
            }
            barx(barid);
        }
    }

    // ---- final output ----
    if (role == 0) {
        *reinterpret_cast<float2*>(&out[(size_t)(bb + r0 + 0) * H_DIM + j0]) = h0r;
        *reinterpret_cast<float2*>(&out[(size_t)(bb + r0 + 1) * H_DIM + j0]) = h1r;
        *reinterpret_cast<float2*>(&out[(size_t)(bb + r0 + 2) * H_DIM + j0]) = h2r;
        *reinterpret_cast<float2*>(&out[(size_t)(bb + r0 + 3) * H_DIM + j0]) = h3r;
    } else if (role == 1) {
        *reinterpret_cast<float2*>(&out[(size_t)(bb + r0 + 4) * H_DIM + j0]) = h0r;
        *reinterpret_cast<float2*>(&out[(size_t)(bb + r0 + 5) * H_DIM + j0]) = h1r;
        *reinterpret_cast<float2*>(&out[(size_t)(bb + r0 + 6) * H_DIM + j0]) = h2r;
        *reinterpret_cast<float2*>(&out[(size_t)(bb + r0 + 7) * H_DIM + j0]) = h3r;
    }
}

extern "C" void kernel_launch(void* const* d_in, const int* in_sizes, int n_in,
                              void* d_out, int out_size) {
    const float* seq  = (const float*)d_in[0];
    const float* W_ih = (const float*)d_in[1];
    const float* W_hh = (const float*)d_in[2];
    const float* b_ih = (const float*)d_in[3];
    const float* b_hh = (const float*)d_in[4];
    float* out = (float*)d_out;

    const int B = out_size / H_DIM;
    const int T = in_sizes[0] / (B * I_DIM);

    cudaFuncSetAttribute(gru_fwd_kernel,
                         cudaFuncAttributeMaxDynamicSharedMemorySize, SMEM_BYTES);

    const int grid = (B + ROWS_PER_CTA - 1) / ROWS_PER_CTA;
    gru_fwd_kernel<<<grid, THREADS, SMEM_BYTES>>>(seq, W_ih, W_hh, b_ih, b_hh,
                                                  out, B, T);
}